// round 4
// baseline (speedup 1.0000x reference)
#include <cuda_runtime.h>
#include <cstdint>
#include <math.h>

#define N_ROWS 32768
#define DIM    64
#define NEMB   8192

// ---- output layout (concatenated reference tuple, all float32) ----
#define OFF_Q    0
#define OFF_LOSS 2097152
#define OFF_IDX  2097153
#define OFF_PERP 2129921
#define OFF_W    2129922
#define OFF_CC   2654210
#define OFF_WS   2662402

// ---- device scratch (no allocations allowed) ----
__device__ int   g_idx[N_ROWS];
__device__ float g_counts[NEMB];
__device__ float g_embsum[NEMB * DIM];
__device__ float g_enormh[NEMB];
__device__ float g_nsum;
__device__ float g_loss;
__device__ float g_plogp;

// ============================================================
// init: zero scratch
// ============================================================
__global__ void k_init() {
    int t = blockIdx.x * 256 + threadIdx.x;
    if (t < NEMB * DIM) g_embsum[t] = 0.f;
    if (t < NEMB)       g_counts[t] = 0.f;
    if (t == 0) { g_nsum = 0.f; g_loss = 0.f; g_plogp = 0.f; }
}

// ============================================================
// 0.5 * ||e_k||^2 per code (warp per code)
// ============================================================
__global__ void k_enorm(const float* __restrict__ w) {
    int code = blockIdx.x * 8 + (threadIdx.x >> 5);
    int lane = threadIdx.x & 31;
    float a = w[code * DIM + lane];
    float b = w[code * DIM + 32 + lane];
    float s = a * a + b * b;
#pragma unroll
    for (int m = 16; m >= 1; m >>= 1) s += __shfl_xor_sync(0xffffffffu, s, m);
    if (lane == 0) g_enormh[code] = 0.5f * s;
}

// ============================================================
// argmin kernel: block = 64 rows, loops over 8192 codes in
// chunks of 64. Score s = x.e - 0.5||e||^2 ; argmax(s) ==
// argmin(distance). Packed f32x2 FMAs: 2 codes per 64-bit acc.
// Thread: tx = tid&7 owns 8 codes of chunk, ty = tid>>3 owns 2 rows.
// ============================================================
#define UNPACK2(v, lo, hi) asm("mov.b64 {%0,%1}, %2;" : "=f"(lo), "=f"(hi) : "l"(v))
#define PACK_DUP(d, a)     asm("mov.b64 %0, {%1,%1};" : "=l"(d) : "f"(a))
#define FMA2(acc, a, b)    asm("fma.rn.f32x2 %0, %1, %2, %0;" : "+l"(acc) : "l"(a), "l"(b))

__global__ void __launch_bounds__(256) k_argmin(const float* __restrict__ x,
                                                const float* __restrict__ w,
                                                float* __restrict__ out_idxf) {
    __shared__ __align__(16) float xs[64 * 65];   // [row][d], padded
    __shared__ __align__(16) float cs[64 * 68];   // [d][code], stride 68 (16B aligned rows)
    __shared__ float sen[64];

    int tid = threadIdx.x;
    int tx = tid & 7;          // code subgroup 0..7
    int ty = tid >> 3;         // row pair 0..31
    int rowBase = blockIdx.x * 64;

    // load 64x64 x-tile (coalesced, conflict-free STS)
#pragma unroll
    for (int i = 0; i < 16; i++) {
        int e = tid + i * 256;
        int r = e >> 6, d = e & 63;
        xs[r * 65 + d] = x[(rowBase + r) * DIM + d];
    }

    float best0 = -3.402823466e38f, best1 = -3.402823466e38f;
    int bi0 = 0, bi1 = 0;

    uint32_t csBase = (uint32_t)__cvta_generic_to_shared(cs);
    const float* xr0 = &xs[(ty * 2 + 0) * 65];
    const float* xr1 = &xs[(ty * 2 + 1) * 65];

    for (int ch = 0; ch < 128; ++ch) {
        __syncthreads();   // previous epilogue done before overwrite
        // load 64-code tile transposed: cs[d*68 + c]
#pragma unroll
        for (int i = 0; i < 16; i++) {
            int e = tid + i * 256;
            int c = e >> 6, d = e & 63;
            cs[d * 68 + c] = w[(ch * 64 + c) * DIM + d];
        }
        if (tid < 64) sen[tid] = g_enormh[ch * 64 + tid];
        __syncthreads();

        unsigned long long a00 = 0, a01 = 0, a02 = 0, a03 = 0;
        unsigned long long a10 = 0, a11 = 0, a12 = 0, a13 = 0;

#pragma unroll 16
        for (int d = 0; d < 64; ++d) {
            float av0 = xr0[d];
            float av1 = xr1[d];
            unsigned long long pa0, pa1;
            PACK_DUP(pa0, av0);
            PACK_DUP(pa1, av1);
            unsigned long long b0, b1, b2, b3;
            uint32_t ba = csBase + (unsigned)(d * 68 + tx * 8) * 4u;
            asm("ld.shared.v2.b64 {%0,%1}, [%2];" : "=l"(b0), "=l"(b1) : "r"(ba));
            asm("ld.shared.v2.b64 {%0,%1}, [%2];" : "=l"(b2), "=l"(b3) : "r"(ba + 16));
            FMA2(a00, pa0, b0); FMA2(a01, pa0, b1); FMA2(a02, pa0, b2); FMA2(a03, pa0, b3);
            FMA2(a10, pa1, b0); FMA2(a11, pa1, b1); FMA2(a12, pa1, b2); FMA2(a13, pa1, b3);
        }

        // epilogue: subtract 0.5||e||^2, running argmax with ascending-j
        // (strict > keeps the lowest index on ties == jnp.argmin semantics)
        int jb = ch * 64 + tx * 8;
        float e0 = sen[tx * 8 + 0], e1 = sen[tx * 8 + 1];
        float e2 = sen[tx * 8 + 2], e3 = sen[tx * 8 + 3];
        float e4 = sen[tx * 8 + 4], e5 = sen[tx * 8 + 5];
        float e6 = sen[tx * 8 + 6], e7 = sen[tx * 8 + 7];
        float lo, hi;
#define UPD(ACC, EA, EB, JOFF, BEST, BIDX)                               \
        { UNPACK2(ACC, lo, hi);                                          \
          float s0 = lo - (EA);  float s1 = hi - (EB);                   \
          if (s0 > BEST) { BEST = s0; BIDX = jb + (JOFF); }              \
          if (s1 > BEST) { BEST = s1; BIDX = jb + (JOFF) + 1; } }
        UPD(a00, e0, e1, 0, best0, bi0); UPD(a01, e2, e3, 2, best0, bi0);
        UPD(a02, e4, e5, 4, best0, bi0); UPD(a03, e6, e7, 6, best0, bi0);
        UPD(a10, e0, e1, 0, best1, bi1); UPD(a11, e2, e3, 2, best1, bi1);
        UPD(a12, e4, e5, 4, best1, bi1); UPD(a13, e6, e7, 6, best1, bi1);
#undef UPD
    }

    // reduce across the 8 tx lanes that share each row (lex: max s, min j)
#pragma unroll
    for (int m = 1; m < 8; m <<= 1) {
        float ob0 = __shfl_xor_sync(0xffffffffu, best0, m);
        int   oj0 = __shfl_xor_sync(0xffffffffu, bi0, m);
        if (ob0 > best0 || (ob0 == best0 && oj0 < bi0)) { best0 = ob0; bi0 = oj0; }
        float ob1 = __shfl_xor_sync(0xffffffffu, best1, m);
        int   oj1 = __shfl_xor_sync(0xffffffffu, bi1, m);
        if (ob1 > best1 || (ob1 == best1 && oj1 < bi1)) { best1 = ob1; bi1 = oj1; }
    }
    if (tx == 0) {
        int r0 = rowBase + ty * 2;
        g_idx[r0]     = bi0;  out_idxf[r0]     = (float)bi0;
        g_idx[r0 + 1] = bi1;  out_idxf[r0 + 1] = (float)bi1;
    }
}

// ============================================================
// scatter: segment counts + segment sums via atomics
// ============================================================
__global__ void k_scatter(const float* __restrict__ x) {
    int t = blockIdx.x * 256 + threadIdx.x;
    if (t >= N_ROWS * DIM) return;
    int n = t >> 6, d = t & 63;
    int idx = g_idx[n];
    atomicAdd(&g_embsum[idx * DIM + d], x[t]);
    if (d == 0) atomicAdd(&g_counts[idx], 1.0f);
}

// ============================================================
// new_cc + global sum(new_cc) + perplexity entropy sum
// ============================================================
__global__ void k_cc(const float* __restrict__ cc_in, float* __restrict__ out_cc) {
    int k = blockIdx.x * 256 + threadIdx.x;
    float c = g_counts[k];
    float ncc = cc_in[k] * 0.99f + 0.01f * c;
    out_cc[k] = ncc;
    float p = c * (1.0f / 32768.0f);
    float pl = p * logf(p + 1e-10f);   // p==0 -> 0
#pragma unroll
    for (int m = 16; m >= 1; m >>= 1) {
        ncc += __shfl_xor_sync(0xffffffffu, ncc, m);
        pl  += __shfl_xor_sync(0xffffffffu, pl, m);
    }
    __shared__ float s1[8], s2[8];
    int wi = threadIdx.x >> 5, lane = threadIdx.x & 31;
    if (lane == 0) { s1[wi] = ncc; s2[wi] = pl; }
    __syncthreads();
    if (threadIdx.x == 0) {
        float a = 0.f, b = 0.f;
        for (int i = 0; i < 8; i++) { a += s1[i]; b += s2[i]; }
        atomicAdd(&g_nsum, a);
        atomicAdd(&g_plogp, b);
    }
}

// ============================================================
// new_ws + new_weight = new_ws / smoothed
// ============================================================
__global__ void k_weight(const float* __restrict__ ws_in, const float* __restrict__ out_cc,
                         float* __restrict__ out_ws, float* __restrict__ out_w) {
    int t = blockIdx.x * 256 + threadIdx.x;
    if (t >= NEMB * DIM) return;
    int k = t >> 6;
    float nws = ws_in[t] * 0.99f + 0.01f * g_embsum[t];
    out_ws[t] = nws;
    float ncc = out_cc[k];
    float n = g_nsum;
    float sm = (ncc + 1e-5f) / (n + (float)NEMB * 1e-5f) * n;
    out_w[t] = nws / sm;
}

// ============================================================
// gather quantized + e_latent_loss sum
// ============================================================
__global__ void k_quant(const float* __restrict__ x, const float* __restrict__ out_w,
                        float* __restrict__ out_q) {
    int t = blockIdx.x * 256 + threadIdx.x;
    if (t >= N_ROWS * DIM) return;
    int n = t >> 6, d = t & 63;
    float q = out_w[g_idx[n] * DIM + d];
    out_q[t] = q;
    float df = q - x[t];
    float v = df * df;
#pragma unroll
    for (int m = 16; m >= 1; m >>= 1) v += __shfl_xor_sync(0xffffffffu, v, m);
    __shared__ float s[8];
    int wi = threadIdx.x >> 5, lane = threadIdx.x & 31;
    if (lane == 0) s[wi] = v;
    __syncthreads();
    if (threadIdx.x == 0) {
        float a = 0.f;
        for (int i = 0; i < 8; i++) a += s[i];
        atomicAdd(&g_loss, a);
    }
}

// ============================================================
// scalars: vq_loss, perplexity
// ============================================================
__global__ void k_scalars(float* __restrict__ out) {
    out[OFF_LOSS] = 0.25f * g_loss * (1.0f / 2097152.0f);
    out[OFF_PERP] = expf(-g_plogp);
}

// ============================================================
extern "C" void kernel_launch(void* const* d_in, const int* in_sizes, int n_in,
                              void* d_out, int out_size) {
    const float* x  = (const float*)d_in[0];  // inputs [8,4096,64]
    const float* w  = (const float*)d_in[1];  // weight [8192,64]
    const float* cc = (const float*)d_in[2];  // ema_cluster_count [8192]
    const float* ws = (const float*)d_in[3];  // ema_weight_sum [8192,64]
    float* out = (float*)d_out;

    k_init   <<<2048, 256>>>();
    k_enorm  <<<1024, 256>>>(w);
    k_argmin <<<512,  256>>>(x, w, out + OFF_IDX);
    k_scatter<<<8192, 256>>>(x);
    k_cc     <<<32,   256>>>(cc, out + OFF_CC);
    k_weight <<<2048, 256>>>(ws, out + OFF_CC, out + OFF_WS, out + OFF_W);
    k_quant  <<<8192, 256>>>(x, out + OFF_W, out + OFF_Q);
    k_scalars<<<1, 1>>>(out);
}

// round 7
// speedup vs baseline: 2.5252x; 2.5252x over previous
#include <cuda_runtime.h>
#include <cstdint>
#include <math.h>

#define N_ROWS 32768
#define DIM    64
#define NEMB   8192

// ---- output layout (concatenated reference tuple, all float32) ----
#define OFF_Q    0
#define OFF_LOSS 2097152
#define OFF_IDX  2097153
#define OFF_PERP 2129921
#define OFF_W    2129922
#define OFF_CC   2654210
#define OFF_WS   2662402

// ---- argmin tiling ----
#define RPB   128          // rows per block
#define CPC   128          // codes per chunk
#define NCH   (NEMB/CPC)   // 64 chunks
#define XSTR  260          // words per d-row of dup-x tile (256 + 4 pad, 16B-multiple!)
#define CSTR  130          // words per d-row of code tile  (128 + 2 pad)
#define SM_FLOATS (64*XSTR + 64*CSTR + CPC)   // 25088 floats = 100352 B

// ---- device scratch ----
__device__ int   g_idx[N_ROWS];
__device__ float g_counts[NEMB];
__device__ float g_embsum[NEMB * DIM];
__device__ float g_enormh[NEMB];
__device__ float g_nsum;
__device__ float g_loss;
__device__ float g_plogp;

// ============================================================
__global__ void k_init() {
    int t = blockIdx.x * 256 + threadIdx.x;
    if (t < NEMB * DIM) g_embsum[t] = 0.f;
    if (t < NEMB)       g_counts[t] = 0.f;
    if (t == 0) { g_nsum = 0.f; g_loss = 0.f; g_plogp = 0.f; }
}

// 0.5*||e_k||^2 per code (warp per code)
__global__ void k_enorm(const float* __restrict__ w) {
    int code = blockIdx.x * 8 + (threadIdx.x >> 5);
    int lane = threadIdx.x & 31;
    float a = w[code * DIM + lane];
    float b = w[code * DIM + 32 + lane];
    float s = a * a + b * b;
#pragma unroll
    for (int m = 16; m >= 1; m >>= 1) s += __shfl_xor_sync(0xffffffffu, s, m);
    if (lane == 0) g_enormh[code] = 0.5f * s;
}

// ============================================================
// argmin: block = 128 rows, loops 64 chunks of 128 codes.
// thread (g = tid&15 -> 8 codes, ry = tid>>4 -> 8 rows), 8x8
// register tile of packed f32x2 accumulators (pair = 2 codes).
// Score s = x.e - 0.5||e||^2 ; argmax(s) == argmin(dist).
// ============================================================
#define UNPACK2(v, lo, hi) asm("mov.b64 {%0,%1}, %2;" : "=f"(lo), "=f"(hi) : "l"(v))
#define FMA2(acc, a, b)    asm("fma.rn.f32x2 %0, %1, %2, %0;" : "+l"(acc) : "l"(a), "l"(b))

__global__ void __launch_bounds__(256, 2) k_argmin(const float* __restrict__ x,
                                                   const float* __restrict__ w,
                                                   float* __restrict__ out_idxf) {
    extern __shared__ __align__(16) float smem[];
    float* xd  = smem;                       // [d][2*row] dup pairs, stride XSTR
    float* cs  = smem + 64 * XSTR;           // [d][j*32 + g*2 + e], stride CSTR
    float* sen = smem + 64 * XSTR + 64 * CSTR;

    int tid = threadIdx.x;
    int g  = tid & 15;     // code group: codes g*8 .. g*8+7 of chunk
    int ry = tid >> 4;     // row group: rows ry*8 .. ry*8+7 of block
    int rowBase = blockIdx.x * RPB;

    // fill dup-transposed x tile (once): xd[d][2r]=xd[d][2r+1]=x[r][d]
#pragma unroll
    for (int i = 0; i < 32; i++) {
        int idx = tid + i * 256;             // 128 rows * 64 d
        int r = idx >> 6, d = idx & 63;
        float v = x[(rowBase + r) * DIM + d];
        *(float2*)&xd[d * XSTR + 2 * r] = make_float2(v, v);
    }

    float best[8];
    int   bi[8];
#pragma unroll
    for (int k = 0; k < 8; k++) { best[k] = -3.402823466e38f; bi[k] = 0; }

    uint32_t xaddr0 = (uint32_t)__cvta_generic_to_shared(xd) + (uint32_t)(ry * 16) * 4u;
    uint32_t baddr0 = (uint32_t)__cvta_generic_to_shared(cs) + (uint32_t)(g * 2) * 4u;

    for (int ch = 0; ch < NCH; ++ch) {
        __syncthreads();   // previous chunk fully consumed before refill
        // fill code tile: code c=g'*8+2j+e, dim d -> cs[d*CSTR + j*32 + g'*2 + e]
#pragma unroll
        for (int i = 0; i < 32; i++) {
            int idx = tid + i * 256;         // 128 codes * 64 d
            int c = idx >> 6, d = idx & 63;  // consecutive tid -> consecutive d (coalesced LDG)
            int m = c & 7;
            cs[d * CSTR + (m >> 1) * 32 + (c >> 3) * 2 + (m & 1)] =
                w[(ch * CPC + c) * DIM + d];
        }
        if (tid < CPC) sen[tid] = g_enormh[ch * CPC + tid];
        __syncthreads();

        unsigned long long acc[8][4];
#pragma unroll
        for (int r = 0; r < 8; r++)
#pragma unroll
            for (int j = 0; j < 4; j++) acc[r][j] = 0ull;

#pragma unroll 2
        for (int d = 0; d < 64; ++d) {
            uint32_t aa = xaddr0 + (uint32_t)(d * XSTR) * 4u;   // 16B-aligned (XSTR*4 % 16 == 0)
            uint32_t ba = baddr0 + (uint32_t)(d * CSTR) * 4u;   // 8B-aligned
            unsigned long long a0,a1,a2,a3,a4,a5,a6,a7, b0,b1,b2,b3;
            asm("ld.shared.v2.b64 {%0,%1}, [%2];" : "=l"(a0), "=l"(a1) : "r"(aa));
            asm("ld.shared.v2.b64 {%0,%1}, [%2];" : "=l"(a2), "=l"(a3) : "r"(aa + 16));
            asm("ld.shared.v2.b64 {%0,%1}, [%2];" : "=l"(a4), "=l"(a5) : "r"(aa + 32));
            asm("ld.shared.v2.b64 {%0,%1}, [%2];" : "=l"(a6), "=l"(a7) : "r"(aa + 48));
            asm("ld.shared.b64 %0, [%1];" : "=l"(b0) : "r"(ba));
            asm("ld.shared.b64 %0, [%1];" : "=l"(b1) : "r"(ba + 128));
            asm("ld.shared.b64 %0, [%1];" : "=l"(b2) : "r"(ba + 256));
            asm("ld.shared.b64 %0, [%1];" : "=l"(b3) : "r"(ba + 384));
            FMA2(acc[0][0], a0, b0); FMA2(acc[0][1], a0, b1); FMA2(acc[0][2], a0, b2); FMA2(acc[0][3], a0, b3);
            FMA2(acc[1][0], a1, b0); FMA2(acc[1][1], a1, b1); FMA2(acc[1][2], a1, b2); FMA2(acc[1][3], a1, b3);
            FMA2(acc[2][0], a2, b0); FMA2(acc[2][1], a2, b1); FMA2(acc[2][2], a2, b2); FMA2(acc[2][3], a2, b3);
            FMA2(acc[3][0], a3, b0); FMA2(acc[3][1], a3, b1); FMA2(acc[3][2], a3, b2); FMA2(acc[3][3], a3, b3);
            FMA2(acc[4][0], a4, b0); FMA2(acc[4][1], a4, b1); FMA2(acc[4][2], a4, b2); FMA2(acc[4][3], a4, b3);
            FMA2(acc[5][0], a5, b0); FMA2(acc[5][1], a5, b1); FMA2(acc[5][2], a5, b2); FMA2(acc[5][3], a5, b3);
            FMA2(acc[6][0], a6, b0); FMA2(acc[6][1], a6, b1); FMA2(acc[6][2], a6, b2); FMA2(acc[6][3], a6, b3);
            FMA2(acc[7][0], a7, b0); FMA2(acc[7][1], a7, b1); FMA2(acc[7][2], a7, b2); FMA2(acc[7][3], a7, b3);
        }

        // epilogue: subtract 0.5||e||^2, running argmax, ascending code
        // order + strict > == lowest-index tie-break (jnp.argmin semantics)
        int cbase = ch * CPC + g * 8;
        float lo, hi;
#pragma unroll
        for (int r = 0; r < 8; r++) {
#pragma unroll
            for (int j = 0; j < 4; j++) {
                UNPACK2(acc[r][j], lo, hi);
                float s0 = lo - sen[g * 8 + 2 * j];
                float s1 = hi - sen[g * 8 + 2 * j + 1];
                if (s0 > best[r]) { best[r] = s0; bi[r] = cbase + 2 * j; }
                if (s1 > best[r]) { best[r] = s1; bi[r] = cbase + 2 * j + 1; }
            }
        }
    }

    // reduce across the 16 g-lanes sharing each row group (lex: max s, min j)
#pragma unroll
    for (int m = 1; m < 16; m <<= 1) {
#pragma unroll
        for (int r = 0; r < 8; r++) {
            float ob = __shfl_xor_sync(0xffffffffu, best[r], m);
            int   oj = __shfl_xor_sync(0xffffffffu, bi[r],   m);
            if (ob > best[r] || (ob == best[r] && oj < bi[r])) { best[r] = ob; bi[r] = oj; }
        }
    }
    if (g == 0) {
#pragma unroll
        for (int r = 0; r < 8; r++) {
            int row = rowBase + ry * 8 + r;
            g_idx[row] = bi[r];
            out_idxf[row] = (float)bi[r];
        }
    }
}

// ============================================================
// scatter: segment counts + segment sums via atomics
// ============================================================
__global__ void k_scatter(const float* __restrict__ x) {
    int t = blockIdx.x * 256 + threadIdx.x;
    if (t >= N_ROWS * DIM) return;
    int n = t >> 6, d = t & 63;
    int idx = g_idx[n];
    atomicAdd(&g_embsum[idx * DIM + d], x[t]);
    if (d == 0) atomicAdd(&g_counts[idx], 1.0f);
}

// ============================================================
__global__ void k_cc(const float* __restrict__ cc_in, float* __restrict__ out_cc) {
    int k = blockIdx.x * 256 + threadIdx.x;
    float c = g_counts[k];
    float ncc = cc_in[k] * 0.99f + 0.01f * c;
    out_cc[k] = ncc;
    float p = c * (1.0f / 32768.0f);
    float pl = p * logf(p + 1e-10f);
#pragma unroll
    for (int m = 16; m >= 1; m >>= 1) {
        ncc += __shfl_xor_sync(0xffffffffu, ncc, m);
        pl  += __shfl_xor_sync(0xffffffffu, pl, m);
    }
    __shared__ float s1[8], s2[8];
    int wi = threadIdx.x >> 5, lane = threadIdx.x & 31;
    if (lane == 0) { s1[wi] = ncc; s2[wi] = pl; }
    __syncthreads();
    if (threadIdx.x == 0) {
        float a = 0.f, b = 0.f;
        for (int i = 0; i < 8; i++) { a += s1[i]; b += s2[i]; }
        atomicAdd(&g_nsum, a);
        atomicAdd(&g_plogp, b);
    }
}

// ============================================================
__global__ void k_weight(const float* __restrict__ ws_in, const float* __restrict__ out_cc,
                         float* __restrict__ out_ws, float* __restrict__ out_w) {
    int t = blockIdx.x * 256 + threadIdx.x;
    if (t >= NEMB * DIM) return;
    int k = t >> 6;
    float nws = ws_in[t] * 0.99f + 0.01f * g_embsum[t];
    out_ws[t] = nws;
    float ncc = out_cc[k];
    float n = g_nsum;
    float sm = (ncc + 1e-5f) / (n + (float)NEMB * 1e-5f) * n;
    out_w[t] = nws / sm;
}

// ============================================================
__global__ void k_quant(const float* __restrict__ x, const float* __restrict__ out_w,
                        float* __restrict__ out_q) {
    int t = blockIdx.x * 256 + threadIdx.x;
    if (t >= N_ROWS * DIM) return;
    int n = t >> 6, d = t & 63;
    float q = out_w[g_idx[n] * DIM + d];
    out_q[t] = q;
    float df = q - x[t];
    float v = df * df;
#pragma unroll
    for (int m = 16; m >= 1; m >>= 1) v += __shfl_xor_sync(0xffffffffu, v, m);
    __shared__ float s[8];
    int wi = threadIdx.x >> 5, lane = threadIdx.x & 31;
    if (lane == 0) s[wi] = v;
    __syncthreads();
    if (threadIdx.x == 0) {
        float a = 0.f;
        for (int i = 0; i < 8; i++) a += s[i];
        atomicAdd(&g_loss, a);
    }
}

// ============================================================
__global__ void k_scalars(float* __restrict__ out) {
    out[OFF_LOSS] = 0.25f * g_loss * (1.0f / 2097152.0f);
    out[OFF_PERP] = expf(-g_plogp);
}

// ============================================================
extern "C" void kernel_launch(void* const* d_in, const int* in_sizes, int n_in,
                              void* d_out, int out_size) {
    const float* x  = (const float*)d_in[0];
    const float* w  = (const float*)d_in[1];
    const float* cc = (const float*)d_in[2];
    const float* ws = (const float*)d_in[3];
    float* out = (float*)d_out;

    static int smem_set = 0;
    if (!smem_set) {
        cudaFuncSetAttribute(k_argmin, cudaFuncAttributeMaxDynamicSharedMemorySize,
                             SM_FLOATS * 4);
        smem_set = 1;
    }

    k_init   <<<2048, 256>>>();
    k_enorm  <<<1024, 256>>>(w);
    k_argmin <<<N_ROWS / RPB, 256, SM_FLOATS * 4>>>(x, w, out + OFF_IDX);
    k_scatter<<<8192, 256>>>(x);
    k_cc     <<<32,   256>>>(cc, out + OFF_CC);
    k_weight <<<2048, 256>>>(ws, out + OFF_CC, out + OFF_WS, out + OFF_W);
    k_quant  <<<8192, 256>>>(x, out + OFF_W, out + OFF_Q);
    k_scalars<<<1, 1>>>(out);
}

// round 9
// speedup vs baseline: 3.3526x; 1.3276x over previous
#include <cuda_runtime.h>
#include <cuda_bf16.h>
#include <cstdint>
#include <math.h>

#define N_ROWS 32768
#define DIM    64
#define NEMB   8192

// ---- output layout (concatenated reference tuple, all float32) ----
#define OFF_Q    0
#define OFF_LOSS 2097152
#define OFF_IDX  2097153
#define OFF_PERP 2129921
#define OFF_W    2129922
#define OFF_CC   2654210
#define OFF_WS   2662402

// ---- argmin tiling ----
#define RPB   128            // rows per block (M)
#define CPC   128            // codes per chunk (N)
#define NCH   (NEMB/CPC)     // 64 chunks

// SMEM layout (bytes). Tiles: 128 rows x 128B (64 bf16), XOR-swizzled.
#define A_OFF      0                      // 3 x 16KB (h,m,l splits of x rows)
#define B_OFF      49152                  // 2 bufs x 3 x 16KB
#define SEN_OFF    147456                 // 2 x 512B (0.5*||e||^2 per chunk)
#define RED_OFF    148480                 // 128 rows x 4 warpcols x 8B
#define SMEM_BYTES 152576

// ---- device scratch ----
__device__ int   g_idx[N_ROWS];
__device__ float g_counts[NEMB];
__device__ float g_embsum[NEMB * DIM];
__device__ float g_enormh[NEMB];
__device__ float g_nsum;
__device__ float g_loss;
__device__ float g_plogp;
// pre-split codebook (3-term bf16 decomposition of w)
__device__ __nv_bfloat16 g_wh[NEMB * DIM];
__device__ __nv_bfloat16 g_wm[NEMB * DIM];
__device__ __nv_bfloat16 g_wl[NEMB * DIM];

// ================= helpers =================
__device__ __forceinline__ uint32_t smem_u32_of(const void* p) {
    uint32_t a;
    asm("{ .reg .u64 t; cvta.to.shared.u64 t, %1; cvt.u32.u64 %0, t; }"
        : "=r"(a) : "l"(p));
    return a;
}
__device__ __forceinline__ void ldmx4(uint32_t& r0, uint32_t& r1, uint32_t& r2,
                                      uint32_t& r3, uint32_t a) {
    asm volatile("ldmatrix.sync.aligned.m8n8.x4.shared.b16 {%0,%1,%2,%3}, [%4];"
                 : "=r"(r0), "=r"(r1), "=r"(r2), "=r"(r3) : "r"(a));
}
__device__ __forceinline__ void mma16816(float& c0, float& c1, float& c2, float& c3,
                                         uint32_t a0, uint32_t a1, uint32_t a2, uint32_t a3,
                                         uint32_t b0, uint32_t b1) {
    asm volatile("mma.sync.aligned.m16n8k16.row.col.f32.bf16.bf16.f32 "
                 "{%0,%1,%2,%3}, {%4,%5,%6,%7}, {%8,%9}, {%0,%1,%2,%3};"
                 : "+f"(c0), "+f"(c1), "+f"(c2), "+f"(c3)
                 : "r"(a0), "r"(a1), "r"(a2), "r"(a3), "r"(b0), "r"(b1));
}
__device__ __forceinline__ void cp16(uint32_t dst, const void* src) {
    asm volatile("cp.async.cg.shared.global [%0], [%1], 16;" :: "r"(dst), "l"(src));
}
#define CP_COMMIT() asm volatile("cp.async.commit_group;" ::: "memory")
#define CP_WAIT0()  asm volatile("cp.async.wait_group 0;" ::: "memory")

__device__ __forceinline__ uint32_t pack_bf2(__nv_bfloat16 a, __nv_bfloat16 b) {
    unsigned short ua = *(unsigned short*)&a, ub = *(unsigned short*)&b;
    return (uint32_t)ua | ((uint32_t)ub << 16);
}
__device__ __forceinline__ unsigned long long pack_key(float s, int j) {
    uint32_t u = __float_as_uint(s);
    u = (u & 0x80000000u) ? ~u : (u | 0x80000000u);   // order-preserving
    return ((unsigned long long)u << 32) | (uint32_t)(~j);  // bigger key = better, ties -> smaller j
}

// ============================================================
__global__ void k_init() {
    int t = blockIdx.x * 256 + threadIdx.x;
    if (t < NEMB * DIM) g_embsum[t] = 0.f;
    if (t < NEMB)       g_counts[t] = 0.f;
    if (t == 0) { g_nsum = 0.f; g_loss = 0.f; g_plogp = 0.f; }
}

// 3-way bf16 split of the codebook
__global__ void k_prep(const float* __restrict__ w) {
    int t = blockIdx.x * 256 + threadIdx.x;
    float v = w[t];
    __nv_bfloat16 h = __float2bfloat16_rn(v);
    float r1 = v - __bfloat162float(h);
    __nv_bfloat16 m = __float2bfloat16_rn(r1);
    float r2 = r1 - __bfloat162float(m);
    __nv_bfloat16 l = __float2bfloat16_rn(r2);
    g_wh[t] = h; g_wm[t] = m; g_wl[t] = l;
}

__global__ void k_enorm(const float* __restrict__ w) {
    int code = blockIdx.x * 8 + (threadIdx.x >> 5);
    int lane = threadIdx.x & 31;
    float a = w[code * DIM + lane];
    float b = w[code * DIM + 32 + lane];
    float s = a * a + b * b;
#pragma unroll
    for (int m = 16; m >= 1; m >>= 1) s += __shfl_xor_sync(0xffffffffu, s, m);
    if (lane == 0) g_enormh[code] = 0.5f * s;
}

// ============================================================
// tensor-core argmin via mma.sync (non-arch-specific HMMA path).
// Block: 128 rows. Per chunk (128 codes): 6 bf16-split products
// accumulated with m16n8k16 mma; epilogue keeps running argmax.
// B tiles double-buffered via cp.async; A tiles SMEM-resident.
// ============================================================
__device__ __forceinline__ void prefetch_chunk(uint32_t sb, int buf, int cbase, int tid) {
    const __nv_bfloat16* wsp0 = g_wh;
    const __nv_bfloat16* wsp1 = g_wm;
    const __nv_bfloat16* wsp2 = g_wl;
#pragma unroll
    for (int i = 0; i < 12; i++) {
        int u = tid + i * 256;                // 3 splits * 128 rows * 8 col16
        int s = u >> 10;
        int rem = u & 1023;
        int row = rem >> 3, c16 = rem & 7;
        uint32_t dst = sb + B_OFF + buf * 49152 + s * 16384 +
                       row * 128 + (((uint32_t)(c16 ^ (row & 7))) << 4);
        const __nv_bfloat16* wsp = (s == 0) ? wsp0 : (s == 1) ? wsp1 : wsp2;
        cp16(dst, wsp + (size_t)(cbase + row) * 64 + c16 * 8);
    }
    if (tid >= 224) {                         // sen: 128 floats
        int u = tid - 224;
        cp16(sb + SEN_OFF + buf * 512 + u * 16, g_enormh + cbase + u * 4);
    }
    CP_COMMIT();
}

__global__ void __launch_bounds__(256, 1) k_argmin_mma(const float* __restrict__ x,
                                                       float* __restrict__ out_idxf) {
    extern __shared__ __align__(16) char smem[];
    uint32_t sb = smem_u32_of(smem);
    int tid = threadIdx.x;
    int wid = tid >> 5;
    int lid = tid & 31;
    int rowBase = blockIdx.x * RPB;

    int wr = wid & 1;          // M slab (64 rows)
    int wc = wid >> 1;         // N slab (32 codes)
    int Mbase = wr * 64;
    int Nbase = wc * 32;

    // ldmatrix lane geometry (same for A and B)
    int ri    = lid & 7;
    int mi    = lid >> 3;
    int rowIn = (mi & 1) * 8 + ri;   // row within 16-row tile
    int half  = mi >> 1;             // col16 half within tile
    uint32_t colk[4];
#pragma unroll
    for (int kt = 0; kt < 4; kt++) colk[kt] = (uint32_t)((kt * 2 + half) ^ ri) << 4;
    uint32_t aLane = sb + A_OFF + (uint32_t)(Mbase + rowIn) * 128;
    uint32_t bLane = sb + B_OFF + (uint32_t)(Nbase + rowIn) * 128;

    // kick off B prefetch for chunk 0
    prefetch_chunk(sb, 0, 0, tid);

    // ---- A fill: split 128x64 f32 rows into 3 swizzled bf16 tiles ----
#pragma unroll
    for (int i = 0; i < 4; i++) {
        int u = tid + i * 256;               // 128 rows * 8 col16
        int row = u >> 3, c16 = u & 7;
        const float* src = x + (size_t)(rowBase + row) * 64 + c16 * 8;
        float4 f0 = *(const float4*)src;
        float4 f1 = *(const float4*)(src + 4);
        float v[8] = {f0.x, f0.y, f0.z, f0.w, f1.x, f1.y, f1.z, f1.w};
        __nv_bfloat16 hb[8], mb[8], lb[8];
#pragma unroll
        for (int j = 0; j < 8; j++) {
            __nv_bfloat16 h = __float2bfloat16_rn(v[j]);
            float r1 = v[j] - __bfloat162float(h);
            __nv_bfloat16 m = __float2bfloat16_rn(r1);
            float r2 = r1 - __bfloat162float(m);
            hb[j] = h; mb[j] = m; lb[j] = __float2bfloat16_rn(r2);
        }
        uint32_t off = (uint32_t)row * 128 + (((uint32_t)(c16 ^ (row & 7))) << 4);
        uint4 ph = make_uint4(pack_bf2(hb[0], hb[1]), pack_bf2(hb[2], hb[3]),
                              pack_bf2(hb[4], hb[5]), pack_bf2(hb[6], hb[7]));
        uint4 pm = make_uint4(pack_bf2(mb[0], mb[1]), pack_bf2(mb[2], mb[3]),
                              pack_bf2(mb[4], mb[5]), pack_bf2(mb[6], mb[7]));
        uint4 pl = make_uint4(pack_bf2(lb[0], lb[1]), pack_bf2(lb[2], lb[3]),
                              pack_bf2(lb[4], lb[5]), pack_bf2(lb[6], lb[7]));
        *(uint4*)(smem + A_OFF + off)           = ph;
        *(uint4*)(smem + A_OFF + 16384 + off)   = pm;
        *(uint4*)(smem + A_OFF + 32768 + off)   = pl;
    }

    CP_WAIT0();
    __syncthreads();

    float best[8];
    int   bi[8];
#pragma unroll
    for (int k = 0; k < 8; k++) { best[k] = -3.402823466e38f; bi[k] = 0; }

    const int pa[6] = {0, 0, 1, 1, 0, 2};
    const int pb[6] = {0, 1, 0, 1, 2, 0};

    for (int ch = 0; ch < NCH; ++ch) {
        int db = ch & 1;
        if (ch + 1 < NCH) prefetch_chunk(sb, db ^ 1, (ch + 1) * CPC, tid);

        float acc[4][4][4];
#pragma unroll
        for (int mt = 0; mt < 4; mt++)
#pragma unroll
            for (int nt = 0; nt < 4; nt++)
#pragma unroll
                for (int q = 0; q < 4; q++) acc[mt][nt][q] = 0.f;

#pragma unroll
        for (int p = 0; p < 6; p++) {
            uint32_t aBase = aLane + pa[p] * 16384;
            uint32_t bBase = bLane + db * 49152 + pb[p] * 16384;
#pragma unroll
            for (int kt = 0; kt < 4; kt++) {
                uint32_t ck = colk[kt];
                uint32_t g0r0, g0r1, g0r2, g0r3, g1r0, g1r1, g1r2, g1r3;
                ldmx4(g0r0, g0r1, g0r2, g0r3, bBase + ck);
                ldmx4(g1r0, g1r1, g1r2, g1r3, bBase + 2048 + ck);
#pragma unroll
                for (int mt = 0; mt < 4; mt++) {
                    uint32_t a0, a1, a2, a3;
                    ldmx4(a0, a1, a2, a3, aBase + mt * 2048 + ck);
                    mma16816(acc[mt][0][0], acc[mt][0][1], acc[mt][0][2], acc[mt][0][3],
                             a0, a1, a2, a3, g0r0, g0r2);
                    mma16816(acc[mt][1][0], acc[mt][1][1], acc[mt][1][2], acc[mt][1][3],
                             a0, a1, a2, a3, g0r1, g0r3);
                    mma16816(acc[mt][2][0], acc[mt][2][1], acc[mt][2][2], acc[mt][2][3],
                             a0, a1, a2, a3, g1r0, g1r2);
                    mma16816(acc[mt][3][0], acc[mt][3][1], acc[mt][3][2], acc[mt][3][3],
                             a0, a1, a2, a3, g1r1, g1r3);
                }
            }
        }

        // ---- epilogue: subtract 0.5||e||^2, running argmax ----
        // ascending n within chunk + strict > == lowest-index tie-break
        const float* senp = (const float*)(smem + SEN_OFF + db * 512);
#pragma unroll
        for (int nt = 0; nt < 4; nt++) {
            int nl = Nbase + nt * 8 + (lid & 3) * 2;
            float2 se = *(const float2*)(senp + nl);
            int jb = ch * CPC + nl;
#pragma unroll
            for (int mt = 0; mt < 4; mt++) {
                float s0 = acc[mt][nt][0] - se.x;
                float s1 = acc[mt][nt][1] - se.y;
                float s2 = acc[mt][nt][2] - se.x;
                float s3 = acc[mt][nt][3] - se.y;
                int r0 = mt * 2, r1 = mt * 2 + 1;
                if (s0 > best[r0]) { best[r0] = s0; bi[r0] = jb; }
                if (s1 > best[r0]) { best[r0] = s1; bi[r0] = jb + 1; }
                if (s2 > best[r1]) { best[r1] = s2; bi[r1] = jb; }
                if (s3 > best[r1]) { best[r1] = s3; bi[r1] = jb + 1; }
            }
        }

        if (ch + 1 < NCH) CP_WAIT0();
        __syncthreads();
    }

    // ---- reduce: lanes sharing a row (t&3), then warps sharing M (wc) ----
    unsigned long long key[8];
#pragma unroll
    for (int rs = 0; rs < 8; rs++) key[rs] = pack_key(best[rs], bi[rs]);
#pragma unroll
    for (int m = 1; m <= 2; m <<= 1) {
#pragma unroll
        for (int rs = 0; rs < 8; rs++) {
            unsigned long long o = __shfl_xor_sync(0xffffffffu, key[rs], m);
            if (o > key[rs]) key[rs] = o;
        }
    }
    unsigned long long* red = (unsigned long long*)(smem + RED_OFF);
    if ((lid & 3) == 0) {
#pragma unroll
        for (int rs = 0; rs < 8; rs++) {
            int mt = rs >> 1, h = rs & 1;
            int row = wr * 64 + mt * 16 + (lid >> 2) + h * 8;   // row within block
            red[row * 4 + wc] = key[rs];
        }
    }
    __syncthreads();
    if (tid < RPB) {
        unsigned long long k = red[tid * 4];
#pragma unroll
        for (int c = 1; c < 4; c++) { unsigned long long o = red[tid * 4 + c]; if (o > k) k = o; }
        int b = (int)(~(uint32_t)k);
        int row = rowBase + tid;
        g_idx[row] = b;
        out_idxf[row] = (float)b;
    }
}

// ============================================================
__global__ void k_scatter(const float* __restrict__ x) {
    int t = blockIdx.x * 256 + threadIdx.x;
    if (t >= N_ROWS * DIM) return;
    int n = t >> 6, d = t & 63;
    int idx = g_idx[n];
    atomicAdd(&g_embsum[idx * DIM + d], x[t]);
    if (d == 0) atomicAdd(&g_counts[idx], 1.0f);
}

// ============================================================
__global__ void k_cc(const float* __restrict__ cc_in, float* __restrict__ out_cc) {
    int k = blockIdx.x * 256 + threadIdx.x;
    float c = g_counts[k];
    float ncc = cc_in[k] * 0.99f + 0.01f * c;
    out_cc[k] = ncc;
    float p = c * (1.0f / 32768.0f);
    float pl = p * logf(p + 1e-10f);
#pragma unroll
    for (int m = 16; m >= 1; m >>= 1) {
        ncc += __shfl_xor_sync(0xffffffffu, ncc, m);
        pl  += __shfl_xor_sync(0xffffffffu, pl, m);
    }
    __shared__ float s1[8], s2[8];
    int wi = threadIdx.x >> 5, lane = threadIdx.x & 31;
    if (lane == 0) { s1[wi] = ncc; s2[wi] = pl; }
    __syncthreads();
    if (threadIdx.x == 0) {
        float a = 0.f, b = 0.f;
        for (int i = 0; i < 8; i++) { a += s1[i]; b += s2[i]; }
        atomicAdd(&g_nsum, a);
        atomicAdd(&g_plogp, b);
    }
}

// ============================================================
__global__ void k_weight(const float* __restrict__ ws_in, const float* __restrict__ out_cc,
                         float* __restrict__ out_ws, float* __restrict__ out_w) {
    int t = blockIdx.x * 256 + threadIdx.x;
    if (t >= NEMB * DIM) return;
    int k = t >> 6;
    float nws = ws_in[t] * 0.99f + 0.01f * g_embsum[t];
    out_ws[t] = nws;
    float ncc = out_cc[k];
    float n = g_nsum;
    float sm = (ncc + 1e-5f) / (n + (float)NEMB * 1e-5f) * n;
    out_w[t] = nws / sm;
}

// ============================================================
__global__ void k_quant(const float* __restrict__ x, const float* __restrict__ out_w,
                        float* __restrict__ out_q) {
    int t = blockIdx.x * 256 + threadIdx.x;
    if (t >= N_ROWS * DIM) return;
    int n = t >> 6, d = t & 63;
    float q = out_w[g_idx[n] * DIM + d];
    out_q[t] = q;
    float df = q - x[t];
    float v = df * df;
#pragma unroll
    for (int m = 16; m >= 1; m >>= 1) v += __shfl_xor_sync(0xffffffffu, v, m);
    __shared__ float s[8];
    int wi = threadIdx.x >> 5, lane = threadIdx.x & 31;
    if (lane == 0) s[wi] = v;
    __syncthreads();
    if (threadIdx.x == 0) {
        float a = 0.f;
        for (int i = 0; i < 8; i++) a += s[i];
        atomicAdd(&g_loss, a);
    }
}

// ============================================================
__global__ void k_scalars(float* __restrict__ out) {
    out[OFF_LOSS] = 0.25f * g_loss * (1.0f / 2097152.0f);
    out[OFF_PERP] = expf(-g_plogp);
}

// ============================================================
extern "C" void kernel_launch(void* const* d_in, const int* in_sizes, int n_in,
                              void* d_out, int out_size) {
    const float* x  = (const float*)d_in[0];
    const float* w  = (const float*)d_in[1];
    const float* cc = (const float*)d_in[2];
    const float* ws = (const float*)d_in[3];
    float* out = (float*)d_out;

    cudaFuncSetAttribute(k_argmin_mma, cudaFuncAttributeMaxDynamicSharedMemorySize,
                         SMEM_BYTES);

    k_init      <<<2048, 256>>>();
    k_prep      <<<2048, 256>>>(w);
    k_enorm     <<<1024, 256>>>(w);
    k_argmin_mma<<<N_ROWS / RPB, 256, SMEM_BYTES>>>(x, out + OFF_IDX);
    k_scatter   <<<8192, 256>>>(x);
    k_cc        <<<32,   256>>>(cc, out + OFF_CC);
    k_weight    <<<2048, 256>>>(ws, out + OFF_CC, out + OFF_WS, out + OFF_W);
    k_quant     <<<8192, 256>>>(x, out + OFF_W, out + OFF_Q);
    k_scalars   <<<1, 1>>>(out);
}